// round 1
// baseline (speedup 1.0000x reference)
#include <cuda_runtime.h>
#include <math.h>

#define NEMB 8192
#define DIM  512
#define NPOS 4096
#define NNEG 16384
#define NPAIR (NPOS + NNEG)
#define INV_T 14.2857142857142857f   /* 1/0.07 */

#define NSPLIT 16
#define BM 128
#define BN 64
#define BK 16
#define COLS_PER_SPLIT (NEMB / NSPLIT)   /* 512 */

/* ---- scratch (device globals: no runtime allocation allowed) ---- */
__device__ float g_e[NEMB * DIM];            /* normalized embeddings, 16 MB */
__device__ float g_pm[NPOS * NSPLIT];        /* per-(row,split) running max  */
__device__ float g_ps[NPOS * NSPLIT];        /* per-(row,split) sum-exp      */
__device__ float g_pos_logit[NPOS];
__device__ float g_acc[3];                   /* loss_sum, pos_sum, neg_sum   */

/* ---------------- init: zero accumulators (runs every replay) ----------- */
__global__ void init_kernel() {
    if (threadIdx.x < 3) g_acc[threadIdx.x] = 0.0f;
}

/* ---------------- normalize rows: one warp per row ---------------------- */
__global__ void __launch_bounds__(256) normalize_kernel(const float* __restrict__ emb) {
    const int warp = threadIdx.x >> 5;
    const int lane = threadIdx.x & 31;
    const int row  = blockIdx.x * 8 + warp;
    const float4* src = (const float4*)(emb + (size_t)row * DIM);
    float4*       dst = (float4*)(g_e + (size_t)row * DIM);
    float4 v[4];
    float ss = 0.0f;
#pragma unroll
    for (int q = 0; q < 4; q++) {
        v[q] = src[lane + 32 * q];
        ss += v[q].x * v[q].x + v[q].y * v[q].y + v[q].z * v[q].z + v[q].w * v[q].w;
    }
#pragma unroll
    for (int off = 16; off; off >>= 1)
        ss += __shfl_xor_sync(0xffffffffu, ss, off);
    const float inv = rsqrtf(ss);   /* ||x|| ~ sqrt(512); 1e-8 clamp unreachable */
#pragma unroll
    for (int q = 0; q < 4; q++) {
        float4 o;
        o.x = v[q].x * inv; o.y = v[q].y * inv; o.z = v[q].z * inv; o.w = v[q].w * inv;
        dst[lane + 32 * q] = o;
    }
}

/* ------------- metrics: one warp per pair (pos then neg) ---------------- */
__global__ void __launch_bounds__(256) metrics_kernel(
    const int* __restrict__ pa, const int* __restrict__ pt,
    const int* __restrict__ na, const int* __restrict__ nt) {
    __shared__ float s_pos, s_neg;
    if (threadIdx.x == 0) { s_pos = 0.0f; s_neg = 0.0f; }
    __syncthreads();

    const int warp = threadIdx.x >> 5;
    const int lane = threadIdx.x & 31;
    const int w    = blockIdx.x * 8 + warp;
    const bool isPos = (w < NPOS);
    int ia, it;
    if (isPos) { ia = pa[w];        it = pt[w];        }
    else       { ia = na[w - NPOS]; it = nt[w - NPOS]; }

    const float4* A = (const float4*)(g_e + (size_t)ia * DIM);
    const float4* B = (const float4*)(g_e + (size_t)it * DIM);
    float d = 0.0f;
#pragma unroll
    for (int q = 0; q < 4; q++) {
        const float4 a = A[lane + 32 * q];
        const float4 b = B[lane + 32 * q];
        d += a.x * b.x + a.y * b.y + a.z * b.z + a.w * b.w;
    }
#pragma unroll
    for (int off = 16; off; off >>= 1)
        d += __shfl_xor_sync(0xffffffffu, d, off);

    if (lane == 0) {
        if (isPos) { g_pos_logit[w] = d * INV_T; atomicAdd(&s_pos, d); }
        else       { atomicAdd(&s_neg, d); }
    }
    __syncthreads();
    if (threadIdx.x == 0) {
        atomicAdd(&g_acc[1], s_pos);
        atomicAdd(&g_acc[2], s_neg);
    }
}

/* -------- fused GEMM + online LSE over a column split ------------------- */
/* grid = (NPOS/BM, NSPLIT), 256 threads. Thread (tx,ty)=(tid&15,tid>>4)    */
/* owns an 8x4 microtile: rows ty*8+i, cols tx*4+j of the 128x64 tile.      */
__global__ void __launch_bounds__(256) lse_gemm_kernel(const int* __restrict__ pa) {
    __shared__ float As[BM][BK + 1];
    __shared__ float Bs[BN][BK + 1];
    __shared__ int   rowsA[BM];

    const int m0  = blockIdx.x * BM;
    const int n0  = blockIdx.y * COLS_PER_SPLIT;
    const int tid = threadIdx.x;
    const int tx  = tid & 15;
    const int ty  = tid >> 4;

    if (tid < BM) rowsA[tid] = pa[m0 + tid];
    __syncthreads();

    float mrow[8], srow[8];
#pragma unroll
    for (int i = 0; i < 8; i++) { mrow[i] = -3.0e38f; srow[i] = 0.0f; }

    for (int nt = 0; nt < COLS_PER_SPLIT / BN; nt++) {
        float acc[8][4];
#pragma unroll
        for (int i = 0; i < 8; i++)
#pragma unroll
            for (int j = 0; j < 4; j++) acc[i][j] = 0.0f;

        for (int kt = 0; kt < DIM / BK; kt++) {
            /* A tile: 128 rows x 16 k = 512 float4, 2 per thread (gather) */
#pragma unroll
            for (int l = 0; l < 2; l++) {
                const int idx = tid + l * 256;
                const int r   = idx >> 2;
                const int kc  = (idx & 3) * 4;
                const float4 v = *(const float4*)(g_e + (size_t)rowsA[r] * DIM + kt * BK + kc);
                As[r][kc + 0] = v.x; As[r][kc + 1] = v.y;
                As[r][kc + 2] = v.z; As[r][kc + 3] = v.w;
            }
            /* B tile: 64 rows x 16 k = 256 float4, 1 per thread */
            {
                const int r  = tid >> 2;
                const int kc = (tid & 3) * 4;
                const float4 v = *(const float4*)(g_e + (size_t)(n0 + nt * BN + r) * DIM + kt * BK + kc);
                Bs[r][kc + 0] = v.x; Bs[r][kc + 1] = v.y;
                Bs[r][kc + 2] = v.z; Bs[r][kc + 3] = v.w;
            }
            __syncthreads();

#pragma unroll
            for (int k = 0; k < BK; k++) {
                float a[8], b[4];
#pragma unroll
                for (int i = 0; i < 8; i++) a[i] = As[ty * 8 + i][k];
#pragma unroll
                for (int j = 0; j < 4; j++) b[j] = Bs[tx * 4 + j][k];
#pragma unroll
                for (int i = 0; i < 8; i++)
#pragma unroll
                    for (int j = 0; j < 4; j++)
                        acc[i][j] = fmaf(a[i], b[j], acc[i][j]);
            }
            __syncthreads();
        }

        /* online LSE update for this 64-column tile */
#pragma unroll
        for (int i = 0; i < 8; i++) {
            const float v0 = acc[i][0] * INV_T;
            const float v1 = acc[i][1] * INV_T;
            const float v2 = acc[i][2] * INV_T;
            const float v3 = acc[i][3] * INV_T;
            const float vmax = fmaxf(fmaxf(v0, v1), fmaxf(v2, v3));
            const float mn   = fmaxf(mrow[i], vmax);
            srow[i] = srow[i] * __expf(mrow[i] - mn)
                    + __expf(v0 - mn) + __expf(v1 - mn)
                    + __expf(v2 - mn) + __expf(v3 - mn);
            mrow[i] = mn;
        }
    }

    /* combine (m,s) across the 16 tx-threads of each row (width-16 shfl) */
#pragma unroll
    for (int i = 0; i < 8; i++) {
        float m = mrow[i], s = srow[i];
#pragma unroll
        for (int off = 8; off; off >>= 1) {
            const float mo = __shfl_down_sync(0xffffffffu, m, off, 16);
            const float so = __shfl_down_sync(0xffffffffu, s, off, 16);
            const float mn = fmaxf(m, mo);
            s = s * __expf(m - mn) + so * __expf(mo - mn);
            m = mn;
        }
        if (tx == 0) {
            const int row = m0 + ty * 8 + i;
            g_pm[row * NSPLIT + blockIdx.y] = m;
            g_ps[row * NSPLIT + blockIdx.y] = s;
        }
    }
}

/* ------------- combine splits, per-row loss, sum ------------------------ */
__global__ void __launch_bounds__(256) reduce_kernel() {
    const int row = blockIdx.x * blockDim.x + threadIdx.x;   /* 0..4095 */
    float mv[NSPLIT];
    float M = -3.0e38f;
#pragma unroll
    for (int j = 0; j < NSPLIT; j++) {
        mv[j] = g_pm[row * NSPLIT + j];
        M = fmaxf(M, mv[j]);
    }
    float S = 0.0f;
#pragma unroll
    for (int j = 0; j < NSPLIT; j++)
        S += g_ps[row * NSPLIT + j] * __expf(mv[j] - M);
    const float lse  = M + logf(S);
    float loss = lse - g_pos_logit[row];

#pragma unroll
    for (int off = 16; off; off >>= 1)
        loss += __shfl_xor_sync(0xffffffffu, loss, off);
    __shared__ float sw[8];
    if ((threadIdx.x & 31) == 0) sw[threadIdx.x >> 5] = loss;
    __syncthreads();
    if (threadIdx.x == 0) {
        float t = 0.0f;
#pragma unroll
        for (int i = 0; i < 8; i++) t += sw[i];
        atomicAdd(&g_acc[0], t);
    }
}

__global__ void finalize_kernel(float* __restrict__ out) {
    out[0] = g_acc[0] * (1.0f / NPOS);
    out[1] = g_acc[1] * (1.0f / NPOS);
    out[2] = g_acc[2] * (1.0f / NNEG);
}

extern "C" void kernel_launch(void* const* d_in, const int* in_sizes, int n_in,
                              void* d_out, int out_size) {
    const float* emb = (const float*)d_in[0];
    const int*   pa  = (const int*)d_in[1];
    const int*   pt  = (const int*)d_in[2];
    const int*   na  = (const int*)d_in[3];
    const int*   nt  = (const int*)d_in[4];
    float*       out = (float*)d_out;

    init_kernel<<<1, 32>>>();
    normalize_kernel<<<NEMB / 8, 256>>>(emb);
    metrics_kernel<<<NPAIR / 8, 256>>>(pa, pt, na, nt);
    lse_gemm_kernel<<<dim3(NPOS / BM, NSPLIT), 256>>>(pa);
    reduce_kernel<<<NPOS / 256, 256>>>();
    finalize_kernel<<<1, 1>>>(out);
}

// round 4
// speedup vs baseline: 7.6034x; 7.6034x over previous
#include <cuda_runtime.h>
#include <cuda_bf16.h>
#include <math.h>
#include <stdint.h>

#define NEMB 8192
#define DIM  512
#define NPOS 4096
#define NNEG 16384
#define NPAIR (NPOS + NNEG)
#define INV_T 14.285714285714286f   /* 1/0.07 */

#define TM 128
#define TN 128
#define KCH 32                      /* k per pipeline stage (bf16 elems) */
#define NST (DIM / KCH)             /* 16 stages */
#define NMT (NPOS / TM)             /* 32 */
#define NNT (NEMB / TN)             /* 64 */

#define ROWB 80                     /* smem row stride bytes: 64B data + 16B pad */

/* ------------------- device scratch (no runtime alloc) ------------------ */
__device__ float          g_e [NEMB * DIM];   /* normalized fp32 (metrics)  */
__device__ __nv_bfloat16  g_eb[NEMB * DIM];   /* normalized bf16 (GEMM)     */
__device__ float          g_ps[NPOS * NNT];   /* per-(row, ntile) sum-exp   */
__device__ float          g_pos_logit[NPOS];
__device__ float          g_acc[3];

/* ----------------------------- PTX helpers ------------------------------ */
__device__ __forceinline__ uint32_t smem_u32(const void* p) {
    uint32_t a;
    asm("{ .reg .u64 t; cvta.to.shared.u64 t, %1; cvt.u32.u64 %0, t; }"
        : "=r"(a) : "l"(p));
    return a;
}
#define CP_ASYNC16(dst, src) \
    asm volatile("cp.async.cg.shared.global [%0],[%1],16;" :: "r"(dst), "l"(src))
#define CP_COMMIT() asm volatile("cp.async.commit_group;" ::: "memory")
#define CP_WAIT(n)  asm volatile("cp.async.wait_group %0;" :: "n"(n) : "memory")

#define LDSM4(r0, r1, r2, r3, a) \
    asm volatile("ldmatrix.sync.aligned.m8n8.x4.shared.b16 {%0,%1,%2,%3}, [%4];" \
                 : "=r"(r0), "=r"(r1), "=r"(r2), "=r"(r3) : "r"(a))

__device__ __forceinline__ void mma16816(float* c, uint32_t a0, uint32_t a1,
                                         uint32_t a2, uint32_t a3,
                                         uint32_t b0, uint32_t b1) {
    asm volatile(
        "mma.sync.aligned.m16n8k16.row.col.f32.bf16.bf16.f32 "
        "{%0,%1,%2,%3},{%4,%5,%6,%7},{%8,%9},{%0,%1,%2,%3};"
        : "+f"(c[0]), "+f"(c[1]), "+f"(c[2]), "+f"(c[3])
        : "r"(a0), "r"(a1), "r"(a2), "r"(a3), "r"(b0), "r"(b1));
}

/* ---------------- init: zero accumulators (runs every replay) ----------- */
__global__ void init_kernel() {
    if (threadIdx.x < 3) g_acc[threadIdx.x] = 0.0f;
}

/* ------------- normalize rows: one warp per row; fp32 + bf16 out -------- */
__global__ void __launch_bounds__(256) normalize_kernel(const float* __restrict__ emb) {
    const int warp = threadIdx.x >> 5;
    const int lane = threadIdx.x & 31;
    const int row  = blockIdx.x * 8 + warp;
    const float4* src = (const float4*)(emb + (size_t)row * DIM);
    float4*       dst = (float4*)(g_e + (size_t)row * DIM);
    __nv_bfloat162* dstb = (__nv_bfloat162*)(g_eb + (size_t)row * DIM);
    float4 v[4];
    float ss = 0.0f;
#pragma unroll
    for (int q = 0; q < 4; q++) {
        v[q] = src[lane + 32 * q];
        ss += v[q].x * v[q].x + v[q].y * v[q].y + v[q].z * v[q].z + v[q].w * v[q].w;
    }
#pragma unroll
    for (int off = 16; off; off >>= 1)
        ss += __shfl_xor_sync(0xffffffffu, ss, off);
    const float inv = rsqrtf(ss);
#pragma unroll
    for (int q = 0; q < 4; q++) {
        float4 o;
        o.x = v[q].x * inv; o.y = v[q].y * inv; o.z = v[q].z * inv; o.w = v[q].w * inv;
        dst[lane + 32 * q] = o;
        const int e2 = (lane + 32 * q) * 2;
        dstb[e2 + 0] = __floats2bfloat162_rn(o.x, o.y);
        dstb[e2 + 1] = __floats2bfloat162_rn(o.z, o.w);
    }
}

/* ------------- metrics: exact fp32 dots, one warp per pair -------------- */
__global__ void __launch_bounds__(256) metrics_kernel(
    const int* __restrict__ pa, const int* __restrict__ pt,
    const int* __restrict__ na, const int* __restrict__ nt) {
    __shared__ float s_pos, s_neg;
    if (threadIdx.x == 0) { s_pos = 0.0f; s_neg = 0.0f; }
    __syncthreads();

    const int warp = threadIdx.x >> 5;
    const int lane = threadIdx.x & 31;
    const int w    = blockIdx.x * 8 + warp;
    const bool isPos = (w < NPOS);
    int ia, it;
    if (isPos) { ia = pa[w];        it = pt[w];        }
    else       { ia = na[w - NPOS]; it = nt[w - NPOS]; }

    const float4* A = (const float4*)(g_e + (size_t)ia * DIM);
    const float4* B = (const float4*)(g_e + (size_t)it * DIM);
    float d = 0.0f;
#pragma unroll
    for (int q = 0; q < 4; q++) {
        const float4 a = A[lane + 32 * q];
        const float4 b = B[lane + 32 * q];
        d += a.x * b.x + a.y * b.y + a.z * b.z + a.w * b.w;
    }
#pragma unroll
    for (int off = 16; off; off >>= 1)
        d += __shfl_xor_sync(0xffffffffu, d, off);

    if (lane == 0) {
        if (isPos) { g_pos_logit[w] = d * INV_T; atomicAdd(&s_pos, d); }
        else       { atomicAdd(&s_neg, d); }
    }
    __syncthreads();
    if (threadIdx.x == 0) {
        atomicAdd(&g_acc[1], s_pos);
        atomicAdd(&g_acc[2], s_neg);
    }
}

/* ---------- mma.sync GEMM tile (128x128, K=512) + fixed-shift sum-exp --- */
__global__ void __launch_bounds__(256) lse_gemm_mma(const int* __restrict__ pa) {
    __shared__ __align__(16) uint8_t sA[2][TM * ROWB];
    __shared__ __align__(16) uint8_t sB[2][TN * ROWB];
    __shared__ int   rowsA[TM];
    __shared__ float rowsum[TM];

    const int tid  = threadIdx.x;
    const int wid  = tid >> 5;
    const int lane = tid & 31;
    const int wm   = wid >> 1;          /* warp m position 0..3 (x32 rows)  */
    const int wn   = wid & 1;           /* warp n position 0..1 (x64 cols)  */
    const int m0   = blockIdx.x * TM;
    const int n0   = blockIdx.y * TN;

    if (tid < TM) { rowsA[tid] = pa[m0 + tid]; rowsum[tid] = 0.0f; }
    __syncthreads();

    const uint32_t sAb = smem_u32(sA);
    const uint32_t sBb = smem_u32(sB);

    /* cp.async thread mapping: idx -> (row, 16B chunk) */
    const int ldr = tid >> 2;           /* 0..63  (plus +64 on 2nd issue)   */
    const int ldc = tid & 3;            /* 16B chunk within 64B k-slab      */

    /* ldmatrix per-thread address components */
    const uint32_t aRow = (uint32_t)(wm * 32 + (lane & 15));
    const uint32_t aKof = (uint32_t)((lane >> 4) * 16);          /* bytes */
    const uint32_t bRow = (uint32_t)(wn * 64 + ((lane & 16) >> 1) + (lane & 7));
    const uint32_t bKof = (uint32_t)((lane & 8) * 2);            /* bytes */

    float acc[2][8][4];
#pragma unroll
    for (int i = 0; i < 2; i++)
#pragma unroll
        for (int j = 0; j < 8; j++)
#pragma unroll
            for (int q = 0; q < 4; q++) acc[i][j][q] = 0.0f;

    /* ---- load stage 0 ---- */
    {
#pragma unroll
        for (int i = 0; i < 2; i++) {
            const int r = ldr + i * 64;
            CP_ASYNC16(sAb + r * ROWB + ldc * 16,
                       g_eb + (size_t)rowsA[r] * DIM + ldc * 8);
            CP_ASYNC16(sBb + r * ROWB + ldc * 16,
                       g_eb + (size_t)(n0 + r) * DIM + ldc * 8);
        }
        CP_COMMIT();
    }

    for (int s = 0; s < NST; s++) {
        if (s + 1 < NST) {
            const int nb = (s + 1) & 1;
            const size_t kb = (size_t)(s + 1) * KCH;
#pragma unroll
            for (int i = 0; i < 2; i++) {
                const int r = ldr + i * 64;
                CP_ASYNC16(sAb + nb * (TM * ROWB) + r * ROWB + ldc * 16,
                           g_eb + (size_t)rowsA[r] * DIM + kb + ldc * 8);
                CP_ASYNC16(sBb + nb * (TN * ROWB) + r * ROWB + ldc * 16,
                           g_eb + (size_t)(n0 + r) * DIM + kb + ldc * 8);
            }
            CP_COMMIT();
            CP_WAIT(1);
        } else {
            CP_WAIT(0);
        }
        __syncthreads();

        const uint32_t aS = sAb + (s & 1) * (TM * ROWB);
        const uint32_t bS = sBb + (s & 1) * (TN * ROWB);
#pragma unroll
        for (int ks = 0; ks < KCH / 16; ks++) {
            uint32_t a[2][4], b[4][4];
#pragma unroll
            for (int mt = 0; mt < 2; mt++)
                LDSM4(a[mt][0], a[mt][1], a[mt][2], a[mt][3],
                      aS + (aRow + mt * 16) * ROWB + ks * 32 + aKof);
#pragma unroll
            for (int j = 0; j < 4; j++)
                LDSM4(b[j][0], b[j][1], b[j][2], b[j][3],
                      bS + (bRow + j * 16) * ROWB + ks * 32 + bKof);
#pragma unroll
            for (int mt = 0; mt < 2; mt++)
#pragma unroll
                for (int j = 0; j < 4; j++) {
                    mma16816(acc[mt][2 * j],     a[mt][0], a[mt][1], a[mt][2], a[mt][3],
                             b[j][0], b[j][1]);
                    mma16816(acc[mt][2 * j + 1], a[mt][0], a[mt][1], a[mt][2], a[mt][3],
                             b[j][2], b[j][3]);
                }
        }
        __syncthreads();
    }

    /* ---- epilogue: fixed-shift sum-exp over each M-row's 128 logits ----
       d0,d1 -> row g; d2,d3 -> row g+8 (g = lane>>2, cols vary with lane&3) */
    const int g  = lane >> 2;
    const int tg = lane & 3;
    float rs[2][2];
#pragma unroll
    for (int mt = 0; mt < 2; mt++) {
        rs[mt][0] = 0.0f; rs[mt][1] = 0.0f;
#pragma unroll
        for (int j = 0; j < 8; j++) {
            rs[mt][0] += __expf(fmaf(acc[mt][j][0], INV_T, -INV_T))
                       + __expf(fmaf(acc[mt][j][1], INV_T, -INV_T));
            rs[mt][1] += __expf(fmaf(acc[mt][j][2], INV_T, -INV_T))
                       + __expf(fmaf(acc[mt][j][3], INV_T, -INV_T));
        }
#pragma unroll
        for (int off = 1; off < 4; off <<= 1) {
            rs[mt][0] += __shfl_xor_sync(0xffffffffu, rs[mt][0], off);
            rs[mt][1] += __shfl_xor_sync(0xffffffffu, rs[mt][1], off);
        }
    }
    if (tg == 0) {
#pragma unroll
        for (int mt = 0; mt < 2; mt++) {
            atomicAdd(&rowsum[wm * 32 + mt * 16 + g],     rs[mt][0]);
            atomicAdd(&rowsum[wm * 32 + mt * 16 + g + 8], rs[mt][1]);
        }
    }
    __syncthreads();
    if (tid < TM)
        g_ps[(size_t)(m0 + tid) * NNT + blockIdx.y] = rowsum[tid];
}

/* ------------- combine splits, per-row loss, block-sum ------------------ */
__global__ void __launch_bounds__(256) reduce_kernel() {
    const int row = blockIdx.x * blockDim.x + threadIdx.x;   /* 0..4095 */
    float S = 0.0f;
#pragma unroll
    for (int j = 0; j < NNT; j++)
        S += g_ps[(size_t)row * NNT + j];
    float loss = INV_T + logf(S) - g_pos_logit[row];

#pragma unroll
    for (int off = 16; off; off >>= 1)
        loss += __shfl_xor_sync(0xffffffffu, loss, off);
    __shared__ float sw[8];
    if ((threadIdx.x & 31) == 0) sw[threadIdx.x >> 5] = loss;
    __syncthreads();
    if (threadIdx.x == 0) {
        float t = 0.0f;
#pragma unroll
        for (int i = 0; i < 8; i++) t += sw[i];
        atomicAdd(&g_acc[0], t);
    }
}

__global__ void finalize_kernel(float* __restrict__ out) {
    out[0] = g_acc[0] * (1.0f / NPOS);
    out[1] = g_acc[1] * (1.0f / NPOS);
    out[2] = g_acc[2] * (1.0f / NNEG);
}

extern "C" void kernel_launch(void* const* d_in, const int* in_sizes, int n_in,
                              void* d_out, int out_size) {
    const float* emb = (const float*)d_in[0];
    const int*   pa  = (const int*)d_in[1];
    const int*   pt  = (const int*)d_in[2];
    const int*   na  = (const int*)d_in[3];
    const int*   nt  = (const int*)d_in[4];
    float*       out = (float*)d_out;

    init_kernel<<<1, 32>>>();
    normalize_kernel<<<NEMB / 8, 256>>>(emb);
    metrics_kernel<<<NPAIR / 8, 256>>>(pa, pt, na, nt);
    lse_gemm_mma<<<dim3(NMT, NNT), 256>>>(pa);
    reduce_kernel<<<NPOS / 256, 256>>>();
    finalize_kernel<<<1, 1>>>(out);
}